// round 2
// baseline (speedup 1.0000x reference)
#include <cuda_runtime.h>

// Pixel-wise diagonal RNN:
//   h_t = leaky_relu(W_ih * x_t + W_hh * h_{t-1} + b_hh), h_0 = 0
// x: (1, T, P) float32 with P = Z*H*W; weights: (P,). Output: (1, T, P).
//
// Pure streaming problem: 419 MB in + 419 MB out + 24 MB weights.
// One thread handles 4 contiguous pixels (float4), h carried in registers.

#ifndef NEG_SLOPE
#define NEG_SLOPE 0.01f
#endif

__global__ __launch_bounds__(256) void pixelwise_rnn_kernel(
    const float4* __restrict__ x,     // (T, P/4)
    const float4* __restrict__ w_ih,  // (P/4)
    const float4* __restrict__ w_hh,  // (P/4)
    const float4* __restrict__ b_hh,  // (P/4)
    float4* __restrict__ out,         // (T, P/4)
    int P4, int T)
{
    int p = blockIdx.x * blockDim.x + threadIdx.x;
    if (p >= P4) return;

    const float4 wi = w_ih[p];
    const float4 wh = w_hh[p];
    const float4 b  = b_hh[p];

    float4 h = make_float4(0.f, 0.f, 0.f, 0.f);

    const float4* xp = x + p;
    float4* op = out + p;

    #pragma unroll 5
    for (int t = 0; t < T; ++t) {
        float4 xv = xp[(size_t)t * P4];
        float4 v;
        v.x = fmaf(wi.x, xv.x, fmaf(wh.x, h.x, b.x));
        v.y = fmaf(wi.y, xv.y, fmaf(wh.y, h.y, b.y));
        v.z = fmaf(wi.z, xv.z, fmaf(wh.z, h.z, b.z));
        v.w = fmaf(wi.w, xv.w, fmaf(wh.w, h.w, b.w));
        // leaky_relu with slope in (0,1): max(v, slope*v)
        h.x = fmaxf(v.x, NEG_SLOPE * v.x);
        h.y = fmaxf(v.y, NEG_SLOPE * v.y);
        h.z = fmaxf(v.z, NEG_SLOPE * v.z);
        h.w = fmaxf(v.w, NEG_SLOPE * v.w);
        op[(size_t)t * P4] = h;
    }
}

extern "C" void kernel_launch(void* const* d_in, const int* in_sizes, int n_in,
                              void* d_out, int out_size)
{
    const float* x    = (const float*)d_in[0];  // (B=1, T, Z, H, W)
    const float* w_ih = (const float*)d_in[1];  // (Z, H, W)
    const float* w_hh = (const float*)d_in[2];
    const float* b_hh = (const float*)d_in[3];
    float* out = (float*)d_out;

    int P = in_sizes[1];            // Z*H*W = 2097152
    int T = in_sizes[0] / P;        // 50
    int P4 = P / 4;                 // divisible: P = 2^21

    int threads = 256;
    int blocks = (P4 + threads - 1) / threads;
    pixelwise_rnn_kernel<<<blocks, threads>>>(
        (const float4*)x, (const float4*)w_ih, (const float4*)w_hh,
        (const float4*)b_hh, (float4*)out, P4, T);
}

// round 4
// speedup vs baseline: 1.1161x; 1.1161x over previous
#include <cuda_runtime.h>

// Pixel-wise diagonal RNN:
//   h_t = leaky_relu(W_ih * x_t + W_hh * h_{t-1} + b_hh), h_0 = 0
// Streaming-bound: 443 MB read + 419 MB write. Strategy:
//  - 2x float4 per thread (32B load granularity, doubled MLP)
//  - __ldcs / __stcs streaming hints (evict-first; no reuse anywhere)
//  - h carried in registers across the T loop

#ifndef NEG_SLOPE
#define NEG_SLOPE 0.01f
#endif

__global__ __launch_bounds__(256) void pixelwise_rnn_kernel(
    const float4* __restrict__ x,     // (T, P/4)
    const float4* __restrict__ w_ih,  // (P/4)
    const float4* __restrict__ w_hh,  // (P/4)
    const float4* __restrict__ b_hh,  // (P/4)
    float4* __restrict__ out,         // (T, P/4)
    int P4, int T)
{
    // each thread owns two adjacent float4s: indices 2*tid, 2*tid+1
    int p = 2 * (blockIdx.x * blockDim.x + threadIdx.x);

    const float4 wi0 = w_ih[p],   wi1 = w_ih[p + 1];
    const float4 wh0 = w_hh[p],   wh1 = w_hh[p + 1];
    const float4 b0  = b_hh[p],   b1  = b_hh[p + 1];

    float4 h0 = make_float4(0.f, 0.f, 0.f, 0.f);
    float4 h1 = make_float4(0.f, 0.f, 0.f, 0.f);

    const float4* xp = x + p;
    float4* op = out + p;

    #pragma unroll 5
    for (int t = 0; t < T; ++t) {
        size_t off = (size_t)t * P4;
        float4 xv0 = __ldcs(xp + off);
        float4 xv1 = __ldcs(xp + off + 1);

        float4 v0, v1;
        v0.x = fmaf(wi0.x, xv0.x, fmaf(wh0.x, h0.x, b0.x));
        v0.y = fmaf(wi0.y, xv0.y, fmaf(wh0.y, h0.y, b0.y));
        v0.z = fmaf(wi0.z, xv0.z, fmaf(wh0.z, h0.z, b0.z));
        v0.w = fmaf(wi0.w, xv0.w, fmaf(wh0.w, h0.w, b0.w));
        v1.x = fmaf(wi1.x, xv1.x, fmaf(wh1.x, h1.x, b1.x));
        v1.y = fmaf(wi1.y, xv1.y, fmaf(wh1.y, h1.y, b1.y));
        v1.z = fmaf(wi1.z, xv1.z, fmaf(wh1.z, h1.z, b1.z));
        v1.w = fmaf(wi1.w, xv1.w, fmaf(wh1.w, h1.w, b1.w));

        // leaky_relu with slope in (0,1): max(v, slope*v)
        h0.x = fmaxf(v0.x, NEG_SLOPE * v0.x);
        h0.y = fmaxf(v0.y, NEG_SLOPE * v0.y);
        h0.z = fmaxf(v0.z, NEG_SLOPE * v0.z);
        h0.w = fmaxf(v0.w, NEG_SLOPE * v0.w);
        h1.x = fmaxf(v1.x, NEG_SLOPE * v1.x);
        h1.y = fmaxf(v1.y, NEG_SLOPE * v1.y);
        h1.z = fmaxf(v1.z, NEG_SLOPE * v1.z);
        h1.w = fmaxf(v1.w, NEG_SLOPE * v1.w);

        __stcs(op + off,     h0);
        __stcs(op + off + 1, h1);
    }
}

extern "C" void kernel_launch(void* const* d_in, const int* in_sizes, int n_in,
                              void* d_out, int out_size)
{
    const float* x    = (const float*)d_in[0];  // (B=1, T, Z, H, W)
    const float* w_ih = (const float*)d_in[1];  // (Z, H, W)
    const float* w_hh = (const float*)d_in[2];
    const float* b_hh = (const float*)d_in[3];
    float* out = (float*)d_out;

    int P = in_sizes[1];            // Z*H*W = 2097152
    int T = in_sizes[0] / P;        // 50
    int P4 = P / 4;                 // 524288

    int threads = 256;
    int pairs = P4 / 2;             // 262144 threads, 2 float4 each
    int blocks = (pairs + threads - 1) / threads;
    pixelwise_rnn_kernel<<<blocks, threads>>>(
        (const float4*)x, (const float4*)w_ih, (const float4*)w_hh,
        (const float4*)b_hh, (float4*)out, P4, T);
}